// round 1
// baseline (speedup 1.0000x reference)
#include <cuda_runtime.h>
#include <math.h>

#define T_TOKENS 16384
#define DIM      768
#define INTER    512
#define NE       8
#define NGROUP   4
#define CAP      16384   // per-expert token capacity (worst case)

// ---------------- scratch (device globals; no allocations) ----------------
__device__ int   g_count[NE];
__device__ int   g_tok[NE * CAP];
__device__ float g_wt [NE * CAP];
// H buffer: 8 routed experts + 1 shared "expert" slot, CAP rows x INTER each
__device__ float g_H[(size_t)(NE + 1) * CAP * INTER];

// ---------------- kernel 0: zero counters ----------------
__global__ void zero_counts_kernel() {
    if (threadIdx.x < NE) g_count[threadIdx.x] = 0;
}

// ---------------- kernel 1: gating ----------------
// 1 warp per token. Computes 8 sigmoid scores, grouped top-2 routing,
// normalized combine weights, scatters (token, weight) into per-expert lists.
__global__ void gate_kernel(const float* __restrict__ x,
                            const float* __restrict__ gw,
                            const float* __restrict__ gb) {
    int warp = threadIdx.x >> 5;
    int lane = threadIdx.x & 31;
    int t = blockIdx.x * 8 + warp;
    if (t >= T_TOKENS) return;

    float acc[NE];
#pragma unroll
    for (int e = 0; e < NE; e++) acc[e] = 0.f;

    const float* xr = x + (size_t)t * DIM;
    for (int j = lane; j < DIM; j += 32) {
        float xv = xr[j];
#pragma unroll
        for (int e = 0; e < NE; e++) acc[e] += xv * gw[e * DIM + j];
    }
#pragma unroll
    for (int off = 16; off > 0; off >>= 1) {
#pragma unroll
        for (int e = 0; e < NE; e++)
            acc[e] += __shfl_xor_sync(0xFFFFFFFF, acc[e], off);
    }

    if (lane == 0) {
        float sc[NE], sb[NE];
#pragma unroll
        for (int e = 0; e < NE; e++) {
            sc[e] = 1.f / (1.f + expf(-acc[e]));   // original scores
            sb[e] = sc[e] + gb[e];                 // biased (selection only)
        }
        // group scores: E/G = 2 -> top-2 of 2 = sum of pair
        float gs[NGROUP];
#pragma unroll
        for (int g = 0; g < NGROUP; g++) gs[g] = sb[2 * g] + sb[2 * g + 1];
        // top-2 groups, stable (lower index wins ties)
        int g1 = 0;
#pragma unroll
        for (int g = 1; g < NGROUP; g++) if (gs[g] > gs[g1]) g1 = g;
        int g2 = -1;
#pragma unroll
        for (int g = 0; g < NGROUP; g++) {
            if (g == g1) continue;
            if (g2 < 0 || gs[g] > gs[g2]) g2 = g;
        }
        // top-2 experts among selected groups, stable
        int   b1 = -1, b2 = -1;
        float v1 = -1e30f, v2 = -1e30f;
#pragma unroll
        for (int e = 0; e < NE; e++) {
            int g = e >> 1;
            if (g != g1 && g != g2) continue;
            float v = sb[e];
            if (v > v1)      { v2 = v1; b2 = b1; v1 = v; b1 = e; }
            else if (v > v2) { v2 = v;  b2 = e; }
        }
        float wa = sc[b1], wb = sc[b2];
        float inv = 1.f / (wa + wb + 1e-6f);
        wa *= inv; wb *= inv;

        int s1 = atomicAdd(&g_count[b1], 1);
        g_tok[b1 * CAP + s1] = t;  g_wt[b1 * CAP + s1] = wa;
        int s2 = atomicAdd(&g_count[b2], 1);
        g_tok[b2 * CAP + s2] = t;  g_wt[b2 * CAP + s2] = wb;
    }
}

// ---------------- kernel 2: stage 1 grouped GEMM ----------------
// H[r, :] = silu(Xg @ w1^T) * (Xg @ w3^T), per expert (e==NE is the shared MLP).
// Tile: 64 rows x 128 cols, K-chunk 16, 256 threads, 4x8 micro-tile x2 GEMMs.
__global__ __launch_bounds__(256, 2)
void stage1_kernel(const float* __restrict__ x,
                   const float* __restrict__ w1,
                   const float* __restrict__ w3,
                   const float* __restrict__ sw1,
                   const float* __restrict__ sw3) {
    const int e  = blockIdx.x >> 8;          // 0..8
    const int mt = blockIdx.x & 255;
    const int cnt = (e == NE) ? T_TOKENS : g_count[e];
    const int m0 = mt * 64;
    if (m0 >= cnt) return;
    const int n0 = blockIdx.y * 128;

    const float* W1 = (e < NE) ? w1 + (size_t)e * INTER * DIM : sw1;
    const float* W3 = (e < NE) ? w3 + (size_t)e * INTER * DIM : sw3;

    __shared__ __align__(16) float As [16][64];
    __shared__ __align__(16) float B1s[16][128];
    __shared__ __align__(16) float B3s[16][128];

    const int tid = threadIdx.x;
    const int tx  = tid & 15;       // 0..15 -> 8 output cols each
    const int ty  = tid >> 4;       // 0..15 -> 4 output rows each

    // A-load mapping: thread -> (row, k-group of 4)
    const int arow = tid >> 2;
    const int ak   = (tid & 3) * 4;
    const int rA   = m0 + arow;
    const bool va  = rA < cnt;
    const int tokA = va ? ((e == NE) ? rA : g_tok[e * CAP + rA]) : 0;
    const float* xA = x + (size_t)tokA * DIM + ak;

    float acc1[4][8], acc3[4][8];
#pragma unroll
    for (int i = 0; i < 4; i++)
#pragma unroll
        for (int j = 0; j < 8; j++) { acc1[i][j] = 0.f; acc3[i][j] = 0.f; }

    for (int k0 = 0; k0 < DIM; k0 += 16) {
        float4 av = make_float4(0.f, 0.f, 0.f, 0.f);
        if (va) av = *(const float4*)(xA + k0);

        float4 b1v[2], b3v[2];
#pragma unroll
        for (int i = 0; i < 2; i++) {
            int idx = tid + i * 256;
            int bn  = idx >> 2;
            int bk  = (idx & 3) * 4;
            b1v[i] = *(const float4*)&W1[(size_t)(n0 + bn) * DIM + k0 + bk];
            b3v[i] = *(const float4*)&W3[(size_t)(n0 + bn) * DIM + k0 + bk];
        }
        __syncthreads();
        As[ak + 0][arow] = av.x; As[ak + 1][arow] = av.y;
        As[ak + 2][arow] = av.z; As[ak + 3][arow] = av.w;
#pragma unroll
        for (int i = 0; i < 2; i++) {
            int idx = tid + i * 256;
            int bn  = idx >> 2;
            int bk  = (idx & 3) * 4;
            B1s[bk + 0][bn] = b1v[i].x; B1s[bk + 1][bn] = b1v[i].y;
            B1s[bk + 2][bn] = b1v[i].z; B1s[bk + 3][bn] = b1v[i].w;
            B3s[bk + 0][bn] = b3v[i].x; B3s[bk + 1][bn] = b3v[i].y;
            B3s[bk + 2][bn] = b3v[i].z; B3s[bk + 3][bn] = b3v[i].w;
        }
        __syncthreads();

#pragma unroll
        for (int k = 0; k < 16; k++) {
            float4 a   = *(const float4*)&As [k][ty * 4];
            float4 p1  = *(const float4*)&B1s[k][tx * 8];
            float4 q1  = *(const float4*)&B1s[k][tx * 8 + 4];
            float4 p3  = *(const float4*)&B3s[k][tx * 8];
            float4 q3  = *(const float4*)&B3s[k][tx * 8 + 4];
            float avr[4] = {a.x, a.y, a.z, a.w};
            float w1r[8] = {p1.x, p1.y, p1.z, p1.w, q1.x, q1.y, q1.z, q1.w};
            float w3r[8] = {p3.x, p3.y, p3.z, p3.w, q3.x, q3.y, q3.z, q3.w};
#pragma unroll
            for (int i = 0; i < 4; i++)
#pragma unroll
                for (int j = 0; j < 8; j++) {
                    acc1[i][j] += avr[i] * w1r[j];
                    acc3[i][j] += avr[i] * w3r[j];
                }
        }
        __syncthreads();
    }

    // epilogue: H = silu(h1) * h3
    const size_t hbase = (size_t)e * CAP * INTER;
#pragma unroll
    for (int i = 0; i < 4; i++) {
        int r = m0 + ty * 4 + i;
        if (r < cnt) {
            float* hrow = &g_H[hbase + (size_t)r * INTER + n0 + tx * 8];
#pragma unroll
            for (int j = 0; j < 8; j++) {
                float h1 = acc1[i][j];
                float h3 = acc3[i][j];
                hrow[j] = (h1 / (1.f + __expf(-h1))) * h3;
            }
        }
    }
}

// ---------------- kernel 3/4: stage 2 grouped GEMM ----------------
// y[r, :] = (H_e[r, :] @ w2_e^T) * combine_weight, scattered into out.
// SHARED=true: expert NE, weight 1, direct store (defines every out element).
// SHARED=false: routed experts, atomicAdd.
template <bool SHARED>
__global__ __launch_bounds__(256, 2)
void stage2_kernel(const float* __restrict__ w2,
                   const float* __restrict__ sw2,
                   float* __restrict__ out) {
    int e, mt;
    if (SHARED) { e = NE; mt = blockIdx.x; }
    else        { e = blockIdx.x >> 8; mt = blockIdx.x & 255; }
    const int cnt = SHARED ? T_TOKENS : g_count[e];
    const int m0 = mt * 64;
    if (m0 >= cnt) return;
    const int n0 = blockIdx.y * 128;

    const float* W = SHARED ? sw2 : w2 + (size_t)e * DIM * INTER;
    const float* Hb = g_H + (size_t)e * CAP * INTER;

    __shared__ __align__(16) float As[16][64];
    __shared__ __align__(16) float Bs[16][128];

    const int tid = threadIdx.x;
    const int tx  = tid & 15;
    const int ty  = tid >> 4;

    const int arow = tid >> 2;
    const int ak   = (tid & 3) * 4;
    const int rA   = m0 + arow;
    const bool va  = rA < cnt;
    const float* hA = Hb + (size_t)rA * INTER + ak;

    float acc[4][8];
#pragma unroll
    for (int i = 0; i < 4; i++)
#pragma unroll
        for (int j = 0; j < 8; j++) acc[i][j] = 0.f;

    for (int k0 = 0; k0 < INTER; k0 += 16) {
        float4 av = make_float4(0.f, 0.f, 0.f, 0.f);
        if (va) av = *(const float4*)(hA + k0);
        float4 bv[2];
#pragma unroll
        for (int i = 0; i < 2; i++) {
            int idx = tid + i * 256;
            int bn  = idx >> 2;
            int bk  = (idx & 3) * 4;
            bv[i] = *(const float4*)&W[(size_t)(n0 + bn) * INTER + k0 + bk];
        }
        __syncthreads();
        As[ak + 0][arow] = av.x; As[ak + 1][arow] = av.y;
        As[ak + 2][arow] = av.z; As[ak + 3][arow] = av.w;
#pragma unroll
        for (int i = 0; i < 2; i++) {
            int idx = tid + i * 256;
            int bn  = idx >> 2;
            int bk  = (idx & 3) * 4;
            Bs[bk + 0][bn] = bv[i].x; Bs[bk + 1][bn] = bv[i].y;
            Bs[bk + 2][bn] = bv[i].z; Bs[bk + 3][bn] = bv[i].w;
        }
        __syncthreads();

#pragma unroll
        for (int k = 0; k < 16; k++) {
            float4 a = *(const float4*)&As[k][ty * 4];
            float4 p = *(const float4*)&Bs[k][tx * 8];
            float4 q = *(const float4*)&Bs[k][tx * 8 + 4];
            float avr[4] = {a.x, a.y, a.z, a.w};
            float wr[8]  = {p.x, p.y, p.z, p.w, q.x, q.y, q.z, q.w};
#pragma unroll
            for (int i = 0; i < 4; i++)
#pragma unroll
                for (int j = 0; j < 8; j++) acc[i][j] += avr[i] * wr[j];
        }
        __syncthreads();
    }

#pragma unroll
    for (int i = 0; i < 4; i++) {
        int r = m0 + ty * 4 + i;
        if (r < cnt) {
            if (SHARED) {
                float* orow = &out[(size_t)r * DIM + n0 + tx * 8];
#pragma unroll
                for (int j = 0; j < 8; j++) orow[j] = acc[i][j];
            } else {
                int   t   = g_tok[e * CAP + r];
                float wgt = g_wt [e * CAP + r];
                float* orow = &out[(size_t)t * DIM + n0 + tx * 8];
#pragma unroll
                for (int j = 0; j < 8; j++)
                    atomicAdd(&orow[j], acc[i][j] * wgt);
            }
        }
    }
}

// ---------------- launch ----------------
extern "C" void kernel_launch(void* const* d_in, const int* in_sizes, int n_in,
                              void* d_out, int out_size) {
    const float* x   = (const float*)d_in[0];
    const float* gw  = (const float*)d_in[1];
    const float* gb  = (const float*)d_in[2];
    const float* w1  = (const float*)d_in[3];
    const float* w2  = (const float*)d_in[4];
    const float* w3  = (const float*)d_in[5];
    const float* sw1 = (const float*)d_in[6];
    const float* sw2 = (const float*)d_in[7];
    const float* sw3 = (const float*)d_in[8];
    float* out = (float*)d_out;

    zero_counts_kernel<<<1, 32>>>();
    gate_kernel<<<T_TOKENS / 8, 256>>>(x, gw, gb);
    stage1_kernel<<<dim3((NE + 1) * 256, INTER / 128), 256>>>(x, w1, w3, sw1, sw3);
    stage2_kernel<true ><<<dim3(256,        DIM / 128), 256>>>(w2, sw2, out);
    stage2_kernel<false><<<dim3(NE * 256,   DIM / 128), 256>>>(w2, sw2, out);
}

// round 5
// speedup vs baseline: 3.1296x; 3.1296x over previous
#include <cuda_runtime.h>
#include <math.h>

#define T_TOKENS 16384
#define DIM      768
#define INTER    512
#define NE       8
#define NGROUP   4
#define CAP      16384

// ---------------- scratch (device globals; no allocations) ----------------
__device__ int   g_count[NE];
__device__ int   g_tok[NE * CAP];
__device__ float g_wt [NE * CAP];
__device__ float g_H[(size_t)(NE + 1) * CAP * INTER];

// ---------------- helpers ----------------
__device__ __forceinline__ unsigned f2tf32(float f) {
    unsigned r; asm("cvt.rna.tf32.f32 %0, %1;" : "=r"(r) : "f"(f)); return r;
}

__device__ __forceinline__ void mma_tf32(float (&d)[4], const unsigned (&a)[4],
                                         const unsigned (&b)[2]) {
    asm volatile(
        "mma.sync.aligned.m16n8k8.row.col.f32.tf32.tf32.f32 "
        "{%0,%1,%2,%3}, {%4,%5,%6,%7}, {%8,%9}, {%0,%1,%2,%3};\n"
        : "+f"(d[0]), "+f"(d[1]), "+f"(d[2]), "+f"(d[3])
        : "r"(a[0]), "r"(a[1]), "r"(a[2]), "r"(a[3]), "r"(b[0]), "r"(b[1]));
}

// ---------------- kernel 0: zero counters ----------------
__global__ void zero_counts_kernel() {
    if (threadIdx.x < NE) g_count[threadIdx.x] = 0;
}

// ---------------- kernel 1: gating (exact fp32) ----------------
__global__ void gate_kernel(const float* __restrict__ x,
                            const float* __restrict__ gw,
                            const float* __restrict__ gb) {
    int warp = threadIdx.x >> 5;
    int lane = threadIdx.x & 31;
    int t = blockIdx.x * 8 + warp;
    if (t >= T_TOKENS) return;

    float acc[NE];
#pragma unroll
    for (int e = 0; e < NE; e++) acc[e] = 0.f;

    const float* xr = x + (size_t)t * DIM;
    for (int j = lane; j < DIM; j += 32) {
        float xv = xr[j];
#pragma unroll
        for (int e = 0; e < NE; e++) acc[e] += xv * gw[e * DIM + j];
    }
#pragma unroll
    for (int off = 16; off > 0; off >>= 1) {
#pragma unroll
        for (int e = 0; e < NE; e++)
            acc[e] += __shfl_xor_sync(0xFFFFFFFF, acc[e], off);
    }

    if (lane == 0) {
        float sc[NE], sb[NE];
#pragma unroll
        for (int e = 0; e < NE; e++) {
            sc[e] = 1.f / (1.f + expf(-acc[e]));
            sb[e] = sc[e] + gb[e];
        }
        float gs[NGROUP];
#pragma unroll
        for (int g = 0; g < NGROUP; g++) gs[g] = sb[2 * g] + sb[2 * g + 1];
        int g1 = 0;
#pragma unroll
        for (int g = 1; g < NGROUP; g++) if (gs[g] > gs[g1]) g1 = g;
        int g2 = -1;
#pragma unroll
        for (int g = 0; g < NGROUP; g++) {
            if (g == g1) continue;
            if (g2 < 0 || gs[g] > gs[g2]) g2 = g;
        }
        int   b1 = -1, b2 = -1;
        float v1 = -1e30f, v2 = -1e30f;
#pragma unroll
        for (int e = 0; e < NE; e++) {
            int g = e >> 1;
            if (g != g1 && g != g2) continue;
            float v = sb[e];
            if (v > v1)      { v2 = v1; b2 = b1; v1 = v; b1 = e; }
            else if (v > v2) { v2 = v;  b2 = e; }
        }
        float wa = sc[b1], wb = sc[b2];
        float inv = 1.f / (wa + wb + 1e-6f);
        wa *= inv; wb *= inv;

        int s1 = atomicAdd(&g_count[b1], 1);
        g_tok[b1 * CAP + s1] = t;  g_wt[b1 * CAP + s1] = wa;
        int s2 = atomicAdd(&g_count[b2], 1);
        g_tok[b2 * CAP + s2] = t;  g_wt[b2 * CAP + s2] = wb;
    }
}

// ---------------- stage 1: H = silu(Xg w1^T) * (Xg w3^T), tf32 MMA ----------
// Tile 64x128, BK=16, 256 threads = 8 warps (2x4), warp tile 32x32.
__global__ __launch_bounds__(256)
void stage1_mma(const float* __restrict__ x,
                const float* __restrict__ w1,
                const float* __restrict__ w3,
                const float* __restrict__ sw1,
                const float* __restrict__ sw3) {
    const int e  = blockIdx.x >> 8;
    const int mt = blockIdx.x & 255;
    const int cnt = (e == NE) ? T_TOKENS : g_count[e];
    const int m0 = mt * 64;
    if (m0 >= cnt) return;
    const int n0 = blockIdx.y * 128;

    const float* W1 = (e < NE) ? w1 + (size_t)e * INTER * DIM : sw1;
    const float* W3 = (e < NE) ? w3 + (size_t)e * INTER * DIM : sw3;

    __shared__ unsigned As [2][16][72];
    __shared__ unsigned B1s[2][16][136];
    __shared__ unsigned B3s[2][16][136];

    const int tid  = threadIdx.x;
    const int lane = tid & 31;
    const int wid  = tid >> 5;
    const int wm   = (wid >> 2) * 32;
    const int wn   = (wid & 3) * 32;

    // gmem load mappings
    const int arow = tid >> 2;            // 0..63
    const int akg  = (tid & 3) * 4;       // 0,4,8,12
    const bool va  = (m0 + arow) < cnt;
    const int tokA = va ? ((e == NE) ? (m0 + arow) : g_tok[e * CAP + m0 + arow]) : 0;
    const float* xA = x + (size_t)tokA * DIM + akg;
    const int bn0 = tid >> 2;             // rows bn0, bn0+64

    float4 aR, b1R[2], b3R[2];
    const float4 Z4 = make_float4(0.f, 0.f, 0.f, 0.f);

#define S1_LOAD(k0)                                                            \
    {                                                                          \
        aR = va ? *(const float4*)(xA + (k0)) : Z4;                            \
        b1R[0] = *(const float4*)&W1[(size_t)(n0 + bn0) * DIM + (k0) + akg];   \
        b1R[1] = *(const float4*)&W1[(size_t)(n0 + bn0 + 64) * DIM + (k0) + akg]; \
        b3R[0] = *(const float4*)&W3[(size_t)(n0 + bn0) * DIM + (k0) + akg];   \
        b3R[1] = *(const float4*)&W3[(size_t)(n0 + bn0 + 64) * DIM + (k0) + akg]; \
    }

#define S1_STORE(buf)                                                          \
    {                                                                          \
        As[buf][akg + 0][arow] = f2tf32(aR.x);                                 \
        As[buf][akg + 1][arow] = f2tf32(aR.y);                                 \
        As[buf][akg + 2][arow] = f2tf32(aR.z);                                 \
        As[buf][akg + 3][arow] = f2tf32(aR.w);                                 \
        B1s[buf][akg + 0][bn0] = f2tf32(b1R[0].x);                             \
        B1s[buf][akg + 1][bn0] = f2tf32(b1R[0].y);                             \
        B1s[buf][akg + 2][bn0] = f2tf32(b1R[0].z);                             \
        B1s[buf][akg + 3][bn0] = f2tf32(b1R[0].w);                             \
        B1s[buf][akg + 0][bn0 + 64] = f2tf32(b1R[1].x);                        \
        B1s[buf][akg + 1][bn0 + 64] = f2tf32(b1R[1].y);                        \
        B1s[buf][akg + 2][bn0 + 64] = f2tf32(b1R[1].z);                        \
        B1s[buf][akg + 3][bn0 + 64] = f2tf32(b1R[1].w);                        \
        B3s[buf][akg + 0][bn0] = f2tf32(b3R[0].x);                             \
        B3s[buf][akg + 1][bn0] = f2tf32(b3R[0].y);                             \
        B3s[buf][akg + 2][bn0] = f2tf32(b3R[0].z);                             \
        B3s[buf][akg + 3][bn0] = f2tf32(b3R[0].w);                             \
        B3s[buf][akg + 0][bn0 + 64] = f2tf32(b3R[1].x);                        \
        B3s[buf][akg + 1][bn0 + 64] = f2tf32(b3R[1].y);                        \
        B3s[buf][akg + 2][bn0 + 64] = f2tf32(b3R[1].z);                        \
        B3s[buf][akg + 3][bn0 + 64] = f2tf32(b3R[1].w);                        \
    }

    float acc1[2][4][4], acc3[2][4][4];
#pragma unroll
    for (int i = 0; i < 2; i++)
#pragma unroll
        for (int j = 0; j < 4; j++)
#pragma unroll
            for (int q = 0; q < 4; q++) { acc1[i][j][q] = 0.f; acc3[i][j][q] = 0.f; }

    const int NKT = DIM / 16;   // 48
    S1_LOAD(0);
    S1_STORE(0);
    __syncthreads();

    for (int kt = 0; kt < NKT; kt++) {
        const int cur = kt & 1;
        if (kt + 1 < NKT) S1_LOAD((kt + 1) * 16);

#pragma unroll
        for (int ks = 0; ks < 2; ks++) {
            const int c = ks * 8 + (lane & 3);
            const int r = lane >> 2;
            unsigned a[2][4];
#pragma unroll
            for (int i = 0; i < 2; i++) {
                int mr = wm + i * 16 + r;
                a[i][0] = As[cur][c][mr];
                a[i][1] = As[cur][c][mr + 8];
                a[i][2] = As[cur][c + 4][mr];
                a[i][3] = As[cur][c + 4][mr + 8];
            }
#pragma unroll
            for (int j = 0; j < 4; j++) {
                int n = wn + j * 8 + r;
                unsigned b1[2] = { B1s[cur][c][n], B1s[cur][c + 4][n] };
                unsigned b3[2] = { B3s[cur][c][n], B3s[cur][c + 4][n] };
#pragma unroll
                for (int i = 0; i < 2; i++) {
                    mma_tf32(acc1[i][j], a[i], b1);
                    mma_tf32(acc3[i][j], a[i], b3);
                }
            }
        }

        if (kt + 1 < NKT) S1_STORE((kt + 1) & 1);
        __syncthreads();
    }

    // epilogue: H = silu(h1) * h3
    const size_t hbase = (size_t)e * CAP * INTER;
    const int r = lane >> 2;
    const int c2 = (lane & 3) * 2;
#pragma unroll
    for (int i = 0; i < 2; i++) {
#pragma unroll
        for (int half = 0; half < 2; half++) {
            int row = m0 + wm + i * 16 + r + half * 8;
            if (row < cnt) {
                float* hrow = &g_H[hbase + (size_t)row * INTER + n0 + wn + c2];
#pragma unroll
                for (int j = 0; j < 4; j++) {
                    float h1a = acc1[i][j][half * 2 + 0];
                    float h1b = acc1[i][j][half * 2 + 1];
                    float h3a = acc3[i][j][half * 2 + 0];
                    float h3b = acc3[i][j][half * 2 + 1];
                    float2 v;
                    v.x = (h1a / (1.f + __expf(-h1a))) * h3a;
                    v.y = (h1b / (1.f + __expf(-h1b))) * h3b;
                    *(float2*)&hrow[j * 8] = v;
                }
            }
        }
    }
#undef S1_LOAD
#undef S1_STORE
}

// ---------------- stage 2: out = (H_e w2^T) * cw, tf32 MMA --------------
template <bool SHARED>
__global__ __launch_bounds__(256)
void stage2_mma(const float* __restrict__ w2,
                const float* __restrict__ sw2,
                float* __restrict__ out) {
    int e, mt;
    if (SHARED) { e = NE; mt = blockIdx.x; }
    else        { e = blockIdx.x >> 8; mt = blockIdx.x & 255; }
    const int cnt = SHARED ? T_TOKENS : g_count[e];
    const int m0 = mt * 64;
    if (m0 >= cnt) return;
    const int n0 = blockIdx.y * 128;

    const float* W  = SHARED ? sw2 : w2 + (size_t)e * DIM * INTER;
    const float* Hb = g_H + (size_t)e * CAP * INTER;

    __shared__ unsigned As[2][16][72];
    __shared__ unsigned Bs[2][16][136];

    const int tid  = threadIdx.x;
    const int lane = tid & 31;
    const int wid  = tid >> 5;
    const int wm   = (wid >> 2) * 32;
    const int wn   = (wid & 3) * 32;

    const int arow = tid >> 2;
    const int akg  = (tid & 3) * 4;
    const bool va  = (m0 + arow) < cnt;
    const float* hA = Hb + (size_t)(m0 + arow) * INTER + akg;
    const int bn0 = tid >> 2;

    float4 aR, bR[2];
    const float4 Z4 = make_float4(0.f, 0.f, 0.f, 0.f);

#define S2_LOAD(k0)                                                            \
    {                                                                          \
        aR = va ? *(const float4*)(hA + (k0)) : Z4;                            \
        bR[0] = *(const float4*)&W[(size_t)(n0 + bn0) * INTER + (k0) + akg];   \
        bR[1] = *(const float4*)&W[(size_t)(n0 + bn0 + 64) * INTER + (k0) + akg]; \
    }

#define S2_STORE(buf)                                                          \
    {                                                                          \
        As[buf][akg + 0][arow] = f2tf32(aR.x);                                 \
        As[buf][akg + 1][arow] = f2tf32(aR.y);                                 \
        As[buf][akg + 2][arow] = f2tf32(aR.z);                                 \
        As[buf][akg + 3][arow] = f2tf32(aR.w);                                 \
        Bs[buf][akg + 0][bn0] = f2tf32(bR[0].x);                               \
        Bs[buf][akg + 1][bn0] = f2tf32(bR[0].y);                               \
        Bs[buf][akg + 2][bn0] = f2tf32(bR[0].z);                               \
        Bs[buf][akg + 3][bn0] = f2tf32(bR[0].w);                               \
        Bs[buf][akg + 0][bn0 + 64] = f2tf32(bR[1].x);                          \
        Bs[buf][akg + 1][bn0 + 64] = f2tf32(bR[1].y);                          \
        Bs[buf][akg + 2][bn0 + 64] = f2tf32(bR[1].z);                          \
        Bs[buf][akg + 3][bn0 + 64] = f2tf32(bR[1].w);                          \
    }

    float acc[2][4][4];
#pragma unroll
    for (int i = 0; i < 2; i++)
#pragma unroll
        for (int j = 0; j < 4; j++)
#pragma unroll
            for (int q = 0; q < 4; q++) acc[i][j][q] = 0.f;

    const int NKT = INTER / 16;   // 32
    S2_LOAD(0);
    S2_STORE(0);
    __syncthreads();

    for (int kt = 0; kt < NKT; kt++) {
        const int cur = kt & 1;
        if (kt + 1 < NKT) S2_LOAD((kt + 1) * 16);

#pragma unroll
        for (int ks = 0; ks < 2; ks++) {
            const int c = ks * 8 + (lane & 3);
            const int r = lane >> 2;
            unsigned a[2][4];
#pragma unroll
            for (int i = 0; i < 2; i++) {
                int mr = wm + i * 16 + r;
                a[i][0] = As[cur][c][mr];
                a[i][1] = As[cur][c][mr + 8];
                a[i][2] = As[cur][c + 4][mr];
                a[i][3] = As[cur][c + 4][mr + 8];
            }
#pragma unroll
            for (int j = 0; j < 4; j++) {
                int n = wn + j * 8 + r;
                unsigned b[2] = { Bs[cur][c][n], Bs[cur][c + 4][n] };
#pragma unroll
                for (int i = 0; i < 2; i++) mma_tf32(acc[i][j], a[i], b);
            }
        }

        if (kt + 1 < NKT) S2_STORE((kt + 1) & 1);
        __syncthreads();
    }

    const int r  = lane >> 2;
    const int c2 = (lane & 3) * 2;
#pragma unroll
    for (int i = 0; i < 2; i++) {
#pragma unroll
        for (int half = 0; half < 2; half++) {
            int row = m0 + wm + i * 16 + r + half * 8;
            if (row < cnt) {
                if (SHARED) {
                    float* orow = &out[(size_t)row * DIM + n0 + wn + c2];
#pragma unroll
                    for (int j = 0; j < 4; j++) {
                        float2 v;
                        v.x = acc[i][j][half * 2 + 0];
                        v.y = acc[i][j][half * 2 + 1];
                        *(float2*)&orow[j * 8] = v;
                    }
                } else {
                    int   t   = g_tok[e * CAP + row];
                    float wgt = g_wt [e * CAP + row];
                    float* orow = &out[(size_t)t * DIM + n0 + wn + c2];
#pragma unroll
                    for (int j = 0; j < 4; j++) {
                        atomicAdd(&orow[j * 8 + 0], acc[i][j][half * 2 + 0] * wgt);
                        atomicAdd(&orow[j * 8 + 1], acc[i][j][half * 2 + 1] * wgt);
                    }
                }
            }
        }
    }
#undef S2_LOAD
#undef S2_STORE
}

// ---------------- launch ----------------
extern "C" void kernel_launch(void* const* d_in, const int* in_sizes, int n_in,
                              void* d_out, int out_size) {
    const float* x   = (const float*)d_in[0];
    const float* gw  = (const float*)d_in[1];
    const float* gb  = (const float*)d_in[2];
    const float* w1  = (const float*)d_in[3];
    const float* w2  = (const float*)d_in[4];
    const float* w3  = (const float*)d_in[5];
    const float* sw1 = (const float*)d_in[6];
    const float* sw2 = (const float*)d_in[7];
    const float* sw3 = (const float*)d_in[8];
    float* out = (float*)d_out;

    zero_counts_kernel<<<1, 32>>>();
    gate_kernel<<<T_TOKENS / 8, 256>>>(x, gw, gb);
    stage1_mma<<<dim3((NE + 1) * 256, INTER / 128), 256>>>(x, w1, w3, sw1, sw3);
    stage2_mma<true ><<<dim3(256,      DIM / 128), 256>>>(w2, sw2, out);
    stage2_mma<false><<<dim3(NE * 256, DIM / 128), 256>>>(w2, sw2, out);
}

// round 8
// speedup vs baseline: 4.1904x; 1.3390x over previous
#include <cuda_runtime.h>
#include <math.h>

#define T_TOKENS 16384
#define DIM      768
#define INTER    512
#define NE       8
#define NGROUP   4
#define CAP      16384

#define PITCH    20                  // words per 16-element row (80B, 16B-aligned, ldsm conflict-free)
#define A_BUF    (64 * PITCH)        // words per A buffer
#define B_BUF    (128 * PITCH)       // words per B buffer

// ---------------- scratch (device globals; no allocations) ----------------
__device__ int   g_count[NE];
__device__ int   g_tok[NE * CAP];
__device__ float g_wt [NE * CAP];
__device__ float g_H[(size_t)(NE + 1) * CAP * INTER];

// ---------------- helpers ----------------
__device__ __forceinline__ unsigned f2tf32(float f) {
    unsigned r; asm("cvt.rna.tf32.f32 %0, %1;" : "=r"(r) : "f"(f)); return r;
}

__device__ __forceinline__ void mma_tf32(float (&d)[4], const unsigned (&a)[4],
                                         const unsigned* b) {
    asm volatile(
        "mma.sync.aligned.m16n8k8.row.col.f32.tf32.tf32.f32 "
        "{%0,%1,%2,%3}, {%4,%5,%6,%7}, {%8,%9}, {%0,%1,%2,%3};\n"
        : "+f"(d[0]), "+f"(d[1]), "+f"(d[2]), "+f"(d[3])
        : "r"(a[0]), "r"(a[1]), "r"(a[2]), "r"(a[3]), "r"(b[0]), "r"(b[1]));
}

__device__ __forceinline__ void ldsm4(unsigned& r0, unsigned& r1, unsigned& r2,
                                      unsigned& r3, unsigned addr) {
    asm volatile("ldmatrix.sync.aligned.m8n8.x4.shared.b16 {%0,%1,%2,%3}, [%4];"
                 : "=r"(r0), "=r"(r1), "=r"(r2), "=r"(r3) : "r"(addr));
}

__device__ __forceinline__ void cvt_sts128(unsigned* dst, float4 v) {
    uint4 u;
    u.x = f2tf32(v.x); u.y = f2tf32(v.y); u.z = f2tf32(v.z); u.w = f2tf32(v.w);
    *(uint4*)dst = u;
}

// ---------------- kernel 0: zero counters ----------------
__global__ void zero_counts_kernel() {
    if (threadIdx.x < NE) g_count[threadIdx.x] = 0;
}

// ---------------- kernel 1: gating (exact fp32) ----------------
__global__ void gate_kernel(const float* __restrict__ x,
                            const float* __restrict__ gw,
                            const float* __restrict__ gb) {
    int warp = threadIdx.x >> 5;
    int lane = threadIdx.x & 31;
    int t = blockIdx.x * 8 + warp;
    if (t >= T_TOKENS) return;

    float acc[NE];
#pragma unroll
    for (int e = 0; e < NE; e++) acc[e] = 0.f;

    const float* xr = x + (size_t)t * DIM;
    for (int j = lane; j < DIM; j += 32) {
        float xv = xr[j];
#pragma unroll
        for (int e = 0; e < NE; e++) acc[e] += xv * gw[e * DIM + j];
    }
#pragma unroll
    for (int off = 16; off > 0; off >>= 1) {
#pragma unroll
        for (int e = 0; e < NE; e++)
            acc[e] += __shfl_xor_sync(0xFFFFFFFF, acc[e], off);
    }

    if (lane == 0) {
        float sc[NE], sb[NE];
#pragma unroll
        for (int e = 0; e < NE; e++) {
            sc[e] = 1.f / (1.f + expf(-acc[e]));
            sb[e] = sc[e] + gb[e];
        }
        float gs[NGROUP];
#pragma unroll
        for (int g = 0; g < NGROUP; g++) gs[g] = sb[2 * g] + sb[2 * g + 1];
        int g1 = 0;
#pragma unroll
        for (int g = 1; g < NGROUP; g++) if (gs[g] > gs[g1]) g1 = g;
        int g2 = -1;
#pragma unroll
        for (int g = 0; g < NGROUP; g++) {
            if (g == g1) continue;
            if (g2 < 0 || gs[g] > gs[g2]) g2 = g;
        }
        int   b1 = -1, b2 = -1;
        float v1 = -1e30f, v2 = -1e30f;
#pragma unroll
        for (int e = 0; e < NE; e++) {
            int g = e >> 1;
            if (g != g1 && g != g2) continue;
            float v = sb[e];
            if (v > v1)      { v2 = v1; b2 = b1; v1 = v; b1 = e; }
            else if (v > v2) { v2 = v;  b2 = e; }
        }
        float wa = sc[b1], wb = sc[b2];
        float inv = 1.f / (wa + wb + 1e-6f);
        wa *= inv; wb *= inv;

        int s1 = atomicAdd(&g_count[b1], 1);
        g_tok[b1 * CAP + s1] = t;  g_wt[b1 * CAP + s1] = wa;
        int s2 = atomicAdd(&g_count[b2], 1);
        g_tok[b2 * CAP + s2] = t;  g_wt[b2 * CAP + s2] = wb;
    }
}

// ---------------- stage 1: H = silu(Xg w1^T) * (Xg w3^T) ----------------
// 64x128 tile, BK=16, 8 warps (2x4) each 32x32. Row-major smem + ldmatrix.
// Dynamic smem layout (words): As[2*A_BUF] | B1[2*B_BUF] | B3[2*B_BUF]
__global__ __launch_bounds__(256)
void stage1_mma(const float* __restrict__ x,
                const float* __restrict__ w1,
                const float* __restrict__ w3,
                const float* __restrict__ sw1,
                const float* __restrict__ sw3) {
    const int e  = blockIdx.x >> 8;
    const int mt = blockIdx.x & 255;
    const int cnt = (e == NE) ? T_TOKENS : g_count[e];
    const int m0 = mt * 64;
    if (m0 >= cnt) return;
    const int n0 = blockIdx.y * 128;

    const float* W1 = (e < NE) ? w1 + (size_t)e * INTER * DIM : sw1;
    const float* W3 = (e < NE) ? w3 + (size_t)e * INTER * DIM : sw3;

    extern __shared__ unsigned smem[];
    unsigned* As = smem;
    unsigned* B1 = smem + 2 * A_BUF;
    unsigned* B3 = smem + 2 * A_BUF + 2 * B_BUF;
    const unsigned sbase = (unsigned)__cvta_generic_to_shared(smem);

    const int tid  = threadIdx.x;
    const int lane = tid & 31;
    const int wid  = tid >> 5;
    const int wm   = (wid >> 2) * 32;
    const int wn   = (wid & 3) * 32;

    // gmem->smem mapping: thread -> (row, 4-word k group)
    const int srow = tid >> 2;            // 0..63
    const int skg  = (tid & 3) * 4;       // 0,4,8,12
    const bool va  = (m0 + srow) < cnt;
    const int tokA = va ? ((e == NE) ? (m0 + srow) : g_tok[e * CAP + m0 + srow]) : 0;
    const float* xA = x + (size_t)tokA * DIM + skg;

    const int aidx  = srow * PITCH + skg;
    const int bidx0 = srow * PITCH + skg;
    const int bidx1 = (srow + 64) * PITCH + skg;

    // ldmatrix per-thread byte addresses (buffer 0, ks 0)
    // A frag i: tiles (row wm+i*16+(t>>3&1)*8+(t&7), k (t>>4)*4)
    const int lt = lane;
    unsigned a_addr[2];
#pragma unroll
    for (int i = 0; i < 2; i++) {
        int row = wm + i * 16 + ((lt >> 3) & 1) * 8 + (lt & 7);
        int kc  = (lt >> 4) * 4;
        a_addr[i] = sbase + (row * PITCH + kc) * 4;
    }
    // B frag pair p: rows wn+p*16+(t>>4)*8+(t&7), k ((t>>3)&1)*4
    unsigned b1_addr[2], b3_addr[2];
#pragma unroll
    for (int p = 0; p < 2; p++) {
        int row = wn + p * 16 + (lt >> 4) * 8 + (lt & 7);
        int kc  = ((lt >> 3) & 1) * 4;
        b1_addr[p] = sbase + (2 * A_BUF + row * PITCH + kc) * 4;
        b3_addr[p] = sbase + (2 * A_BUF + 2 * B_BUF + row * PITCH + kc) * 4;
    }

    float4 aR, b1R[2], b3R[2];
    const float4 Z4 = make_float4(0.f, 0.f, 0.f, 0.f);

#define S1_LOAD(k0)                                                            \
    {                                                                          \
        aR = va ? *(const float4*)(xA + (k0)) : Z4;                            \
        b1R[0] = *(const float4*)&W1[(size_t)(n0 + srow) * DIM + (k0) + skg];  \
        b1R[1] = *(const float4*)&W1[(size_t)(n0 + srow + 64) * DIM + (k0) + skg]; \
        b3R[0] = *(const float4*)&W3[(size_t)(n0 + srow) * DIM + (k0) + skg];  \
        b3R[1] = *(const float4*)&W3[(size_t)(n0 + srow + 64) * DIM + (k0) + skg]; \
    }

#define S1_STORE(buf)                                                          \
    {                                                                          \
        cvt_sts128(As + (buf) * A_BUF + aidx, aR);                             \
        cvt_sts128(B1 + (buf) * B_BUF + bidx0, b1R[0]);                        \
        cvt_sts128(B1 + (buf) * B_BUF + bidx1, b1R[1]);                        \
        cvt_sts128(B3 + (buf) * B_BUF + bidx0, b3R[0]);                        \
        cvt_sts128(B3 + (buf) * B_BUF + bidx1, b3R[1]);                        \
    }

    float acc1[2][4][4], acc3[2][4][4];
#pragma unroll
    for (int i = 0; i < 2; i++)
#pragma unroll
        for (int j = 0; j < 4; j++)
#pragma unroll
            for (int q = 0; q < 4; q++) { acc1[i][j][q] = 0.f; acc3[i][j][q] = 0.f; }

    const int NKT = DIM / 16;   // 48
    S1_LOAD(0);
    S1_STORE(0);
    __syncthreads();

    for (int kt = 0; kt < NKT; kt++) {
        const unsigned abuf = (kt & 1) * (A_BUF * 4);
        const unsigned bbuf = (kt & 1) * (B_BUF * 4);
        if (kt + 1 < NKT) S1_LOAD((kt + 1) * 16);

#pragma unroll
        for (int ks = 0; ks < 2; ks++) {
            const unsigned ko = ks * 32;    // +8 words
            unsigned a[2][4];
            ldsm4(a[0][0], a[0][1], a[0][2], a[0][3], a_addr[0] + abuf + ko);
            ldsm4(a[1][0], a[1][1], a[1][2], a[1][3], a_addr[1] + abuf + ko);
            unsigned b1r[8], b3r[8];
            ldsm4(b1r[0], b1r[1], b1r[2], b1r[3], b1_addr[0] + bbuf + ko);
            ldsm4(b1r[4], b1r[5], b1r[6], b1r[7], b1_addr[1] + bbuf + ko);
            ldsm4(b3r[0], b3r[1], b3r[2], b3r[3], b3_addr[0] + bbuf + ko);
            ldsm4(b3r[4], b3r[5], b3r[6], b3r[7], b3_addr[1] + bbuf + ko);
#pragma unroll
            for (int j = 0; j < 4; j++) {
#pragma unroll
                for (int i = 0; i < 2; i++) {
                    mma_tf32(acc1[i][j], a[i], &b1r[j * 2]);
                    mma_tf32(acc3[i][j], a[i], &b3r[j * 2]);
                }
            }
        }

        if (kt + 1 < NKT) S1_STORE((kt + 1) & 1);
        __syncthreads();
    }

    // epilogue: H = silu(h1) * h3
    const size_t hbase = (size_t)e * CAP * INTER;
    const int r = lane >> 2;
    const int c2 = (lane & 3) * 2;
#pragma unroll
    for (int i = 0; i < 2; i++) {
#pragma unroll
        for (int half = 0; half < 2; half++) {
            int row = m0 + wm + i * 16 + r + half * 8;
            if (row < cnt) {
                float* hrow = &g_H[hbase + (size_t)row * INTER + n0 + wn + c2];
#pragma unroll
                for (int j = 0; j < 4; j++) {
                    float h1a = acc1[i][j][half * 2 + 0];
                    float h1b = acc1[i][j][half * 2 + 1];
                    float h3a = acc3[i][j][half * 2 + 0];
                    float h3b = acc3[i][j][half * 2 + 1];
                    float2 v;
                    v.x = (h1a / (1.f + __expf(-h1a))) * h3a;
                    v.y = (h1b / (1.f + __expf(-h1b))) * h3b;
                    *(float2*)&hrow[j * 8] = v;
                }
            }
        }
    }
#undef S1_LOAD
#undef S1_STORE
}

// ---------------- stage 2: out = (H_e w2^T) * cw ----------------
template <bool SHARED>
__global__ __launch_bounds__(256)
void stage2_mma(const float* __restrict__ w2,
                const float* __restrict__ sw2,
                float* __restrict__ out) {
    int e, mt;
    if (SHARED) { e = NE; mt = blockIdx.x; }
    else        { e = blockIdx.x >> 8; mt = blockIdx.x & 255; }
    const int cnt = SHARED ? T_TOKENS : g_count[e];
    const int m0 = mt * 64;
    if (m0 >= cnt) return;
    const int n0 = blockIdx.y * 128;

    const float* W  = SHARED ? sw2 : w2 + (size_t)e * DIM * INTER;
    const float* Hb = g_H + (size_t)e * CAP * INTER;

    __shared__ unsigned As[2 * A_BUF];
    __shared__ unsigned Bs[2 * B_BUF];

    const int tid  = threadIdx.x;
    const int lane = tid & 31;
    const int wid  = tid >> 5;
    const int wm   = (wid >> 2) * 32;
    const int wn   = (wid & 3) * 32;

    const int srow = tid >> 2;
    const int skg  = (tid & 3) * 4;
    const bool va  = (m0 + srow) < cnt;
    const float* hA = Hb + (size_t)(m0 + srow) * INTER + skg;

    const int aidx  = srow * PITCH + skg;
    const int bidx0 = srow * PITCH + skg;
    const int bidx1 = (srow + 64) * PITCH + skg;

    const unsigned abase = (unsigned)__cvta_generic_to_shared(As);
    const unsigned bbase = (unsigned)__cvta_generic_to_shared(Bs);
    const int lt = lane;
    unsigned a_addr[2];
#pragma unroll
    for (int i = 0; i < 2; i++) {
        int row = wm + i * 16 + ((lt >> 3) & 1) * 8 + (lt & 7);
        int kc  = (lt >> 4) * 4;
        a_addr[i] = abase + (row * PITCH + kc) * 4;
    }
    unsigned b_addr[2];
#pragma unroll
    for (int p = 0; p < 2; p++) {
        int row = wn + p * 16 + (lt >> 4) * 8 + (lt & 7);
        int kc  = ((lt >> 3) & 1) * 4;
        b_addr[p] = bbase + (row * PITCH + kc) * 4;
    }

    float4 aR, bR[2];
    const float4 Z4 = make_float4(0.f, 0.f, 0.f, 0.f);

#define S2_LOAD(k0)                                                            \
    {                                                                          \
        aR = va ? *(const float4*)(hA + (k0)) : Z4;                            \
        bR[0] = *(const float4*)&W[(size_t)(n0 + srow) * INTER + (k0) + skg];  \
        bR[1] = *(const float4*)&W[(size_t)(n0 + srow + 64) * INTER + (k0) + skg]; \
    }

#define S2_STORE(buf)                                                          \
    {                                                                          \
        cvt_sts128(As + (buf) * A_BUF + aidx, aR);                             \
        cvt_sts128(Bs + (buf) * B_BUF + bidx0, bR[0]);                         \
        cvt_sts128(Bs + (buf) * B_BUF + bidx1, bR[1]);                         \
    }

    float acc[2][4][4];
#pragma unroll
    for (int i = 0; i < 2; i++)
#pragma unroll
        for (int j = 0; j < 4; j++)
#pragma unroll
            for (int q = 0; q < 4; q++) acc[i][j][q] = 0.f;

    const int NKT = INTER / 16;   // 32
    S2_LOAD(0);
    S2_STORE(0);
    __syncthreads();

    for (int kt = 0; kt < NKT; kt++) {
        const unsigned abuf = (kt & 1) * (A_BUF * 4);
        const unsigned bbuf = (kt & 1) * (B_BUF * 4);
        if (kt + 1 < NKT) S2_LOAD((kt + 1) * 16);

#pragma unroll
        for (int ks = 0; ks < 2; ks++) {
            const unsigned ko = ks * 32;
            unsigned a[2][4];
            ldsm4(a[0][0], a[0][1], a[0][2], a[0][3], a_addr[0] + abuf + ko);
            ldsm4(a[1][0], a[1][1], a[1][2], a[1][3], a_addr[1] + abuf + ko);
            unsigned br[8];
            ldsm4(br[0], br[1], br[2], br[3], b_addr[0] + bbuf + ko);
            ldsm4(br[4], br[5], br[6], br[7], b_addr[1] + bbuf + ko);
#pragma unroll
            for (int j = 0; j < 4; j++)
#pragma unroll
                for (int i = 0; i < 2; i++)
                    mma_tf32(acc[i][j], a[i], &br[j * 2]);
        }

        if (kt + 1 < NKT) S2_STORE((kt + 1) & 1);
        __syncthreads();
    }

    const int r  = lane >> 2;
    const int c2 = (lane & 3) * 2;
#pragma unroll
    for (int i = 0; i < 2; i++) {
#pragma unroll
        for (int half = 0; half < 2; half++) {
            int row = m0 + wm + i * 16 + r + half * 8;
            if (row < cnt) {
                if (SHARED) {
                    float* orow = &out[(size_t)row * DIM + n0 + wn + c2];
#pragma unroll
                    for (int j = 0; j < 4; j++) {
                        float2 v;
                        v.x = acc[i][j][half * 2 + 0];
                        v.y = acc[i][j][half * 2 + 1];
                        *(float2*)&orow[j * 8] = v;
                    }
                } else {
                    int   t   = g_tok[e * CAP + row];
                    float wgt = g_wt [e * CAP + row];
                    float* orow = &out[(size_t)t * DIM + n0 + wn + c2];
#pragma unroll
                    for (int j = 0; j < 4; j++) {
                        atomicAdd(&orow[j * 8 + 0], acc[i][j][half * 2 + 0] * wgt);
                        atomicAdd(&orow[j * 8 + 1], acc[i][j][half * 2 + 1] * wgt);
                    }
                }
            }
        }
    }
#undef S2_LOAD
#undef S2_STORE
}

// ---------------- launch ----------------
extern "C" void kernel_launch(void* const* d_in, const int* in_sizes, int n_in,
                              void* d_out, int out_size) {
    const float* x   = (const float*)d_in[0];
    const float* gw  = (const float*)d_in[1];
    const float* gb  = (const float*)d_in[2];
    const float* w1  = (const float*)d_in[3];
    const float* w2  = (const float*)d_in[4];
    const float* w3  = (const float*)d_in[5];
    const float* sw1 = (const float*)d_in[6];
    const float* sw2 = (const float*)d_in[7];
    const float* sw3 = (const float*)d_in[8];
    float* out = (float*)d_out;

    const int s1_smem = (2 * A_BUF + 4 * B_BUF) * 4;   // 51200 bytes
    cudaFuncSetAttribute(stage1_mma, cudaFuncAttributeMaxDynamicSharedMemorySize, s1_smem);

    zero_counts_kernel<<<1, 32>>>();
    gate_kernel<<<T_TOKENS / 8, 256>>>(x, gw, gb);
    stage1_mma<<<dim3((NE + 1) * 256, INTER / 128), 256, s1_smem>>>(x, w1, w3, sw1, sw3);
    stage2_mma<true ><<<dim3(256,      DIM / 128), 256>>>(w2, sw2, out);
    stage2_mma<false><<<dim3(NE * 256, DIM / 128), 256>>>(w2, sw2, out);
}